// round 8
// baseline (speedup 1.0000x reference)
#include <cuda_runtime.h>
#include <cuda_bf16.h>
#include <float.h>
#include <stdint.h>

#define Bb 4
#define Cc 256
#define C8 32
#define Hh 64
#define Ww 64
#define HW 4096

// ===================== helpers =============================================
__device__ __forceinline__ uint32_t smem_u32(const void* p) {
    uint32_t a;
    asm("{ .reg .u64 t; cvta.to.shared.u64 t, %1; cvt.u32.u64 %0, t; }"
        : "=r"(a) : "l"(p));
    return a;
}
#define SWZ128(off) ((off) ^ (((off) >> 3) & 0x70))

__device__ __forceinline__ void ldsm_x4(uint32_t (&r)[4], uint32_t addr) {
    asm volatile("ldmatrix.sync.aligned.m8n8.x4.shared.b16 {%0,%1,%2,%3}, [%4];"
                 : "=r"(r[0]), "=r"(r[1]), "=r"(r[2]), "=r"(r[3]) : "r"(addr));
}

__device__ __forceinline__ void mma_bf16(float (&d)[4], const uint32_t (&a)[4],
                                         uint32_t b0, uint32_t b1) {
    asm volatile(
        "mma.sync.aligned.m16n8k16.row.col.f32.bf16.bf16.f32 "
        "{%0,%1,%2,%3}, {%4,%5,%6,%7}, {%8,%9}, {%0,%1,%2,%3};"
        : "+f"(d[0]), "+f"(d[1]), "+f"(d[2]), "+f"(d[3])
        : "r"(a[0]), "r"(a[1]), "r"(a[2]), "r"(a[3]), "r"(b0), "r"(b1));
}

#define CP_ASYNC16(dst, src) \
    asm volatile("cp.async.cg.shared.global [%0], [%1], 16;" :: "r"(dst), "l"(src) : "memory")
#define CP_COMMIT()  asm volatile("cp.async.commit_group;" ::: "memory")
#define CP_WAIT1()   asm volatile("cp.async.wait_group 1;" ::: "memory")
#define CP_WAIT0()   asm volatile("cp.async.wait_group 0;" ::: "memory")

__device__ __forceinline__ void split_bf16(float v, uint16_t& h, uint16_t& l) {
    __nv_bfloat16 hb = __float2bfloat16_rn(v);
    __nv_bfloat16 lb = __float2bfloat16_rn(v - __bfloat162float(hb));
    h = __bfloat16_as_ushort(hb);
    l = __bfloat16_as_ushort(lb);
}

// ===================== scratch =============================================
__device__ float g_q[Bb * C8 * HW];            // exact fp32 [b][c][hw]
__device__ float g_k[Bb * C8 * HW];
__device__ float g_vt[Bb * HW * Cc];           // NHWC value: [b][p][c]
__device__ float g_S[Bb * HW];
__device__ int   g_arg[Bb * HW];
__device__ int   g_flag[Bb * HW];
// split-bf16 q/k, [b][hw][c32] rows of 64B
__device__ __nv_bfloat16 g_qh[Bb * HW * 32];
__device__ __nv_bfloat16 g_ql[Bb * HW * 32];
__device__ __nv_bfloat16 g_kh[Bb * HW * 32];
__device__ __nv_bfloat16 g_kl[Bb * HW * 32];
// NHWC bf16, zero halo: [B][66][66][hi 512 | lo 512]
__device__ __nv_bfloat16 g_Xt[(size_t)Bb * 66 * 66 * 1024];
// conv weights split: [seg(hi0/lo1)][tap9][o 256][c 512] bf16
__device__ __nv_bfloat16 g_Wa[2 * 9 * 256 * 512];
// v weights split: [o 256][c 256] bf16
__device__ __nv_bfloat16 g_Wvh[256 * 256];
__device__ __nv_bfloat16 g_Wvl[256 * 256];

// ===================== fused q+k projection =================================
// fp32 out [c][hw] (for exact recheck) + split-bf16 transposed [hw][c] tiles
__global__ __launch_bounds__(256) void gemm_qk(const float* __restrict__ cross_x,
                                               const float* __restrict__ front_x,
                                               const float* __restrict__ Wq,
                                               const float* __restrict__ bq,
                                               const float* __restrict__ Wk,
                                               const float* __restrict__ bk) {
    __shared__ float Xs[16][128];
    __shared__ float Ws[16][36];
    __shared__ float Ts[128][33];
    const int b   = blockIdx.z;
    const int sel = blockIdx.y;                 // 0 -> q, 1 -> k
    const int hw0 = blockIdx.x * 128;
    const int tid = threadIdx.x;
    const int hid = tid & 31;
    const int oid = tid >> 5;

    const float* X    = sel ? front_x : cross_x;
    const float* Wm   = sel ? Wk : Wq;
    const float* bias = sel ? bk : bq;
    float*       out  = sel ? g_k : g_q;

    const float* xb = X + (size_t)b * Cc * HW;
    float acc[4][4];
#pragma unroll
    for (int n = 0; n < 4; n++)
#pragma unroll
        for (int m = 0; m < 4; m++) acc[n][m] = 0.f;

    for (int c0 = 0; c0 < Cc; c0 += 16) {
        __syncthreads();
#pragma unroll
        for (int r = 0; r < 8; r++) {
            int idx = tid + r * 256;
            int cc = idx >> 7, h = idx & 127;
            Xs[cc][h] = xb[(size_t)(c0 + cc) * HW + hw0 + h];
        }
#pragma unroll
        for (int r = 0; r < 2; r++) {
            int idx = tid + r * 256;
            int cc = idx >> 5, o = idx & 31;
            Ws[cc][o] = Wm[(size_t)o * Cc + c0 + cc];
        }
        __syncthreads();
#pragma unroll
        for (int cc = 0; cc < 16; cc++) {
            float4 wv = *(const float4*)&Ws[cc][oid * 4];
            float4 xv = *(const float4*)&Xs[cc][hid * 4];
            float wa[4] = {wv.x, wv.y, wv.z, wv.w};
            float xa[4] = {xv.x, xv.y, xv.z, xv.w};
#pragma unroll
            for (int n = 0; n < 4; n++)
#pragma unroll
                for (int m = 0; m < 4; m++) acc[n][m] += wa[n] * xa[m];
        }
    }
#pragma unroll
    for (int n = 0; n < 4; n++) {
        int o = oid * 4 + n;
        float bi = bias[o];
        float4 res;
        res.x = acc[n][0] + bi;
        res.y = acc[n][1] + bi;
        res.z = acc[n][2] + bi;
        res.w = acc[n][3] + bi;
        *(float4*)&out[(size_t)b * C8 * HW + (size_t)o * HW + hw0 + hid * 4] = res;
        Ts[hid * 4 + 0][o] = res.x;
        Ts[hid * 4 + 1][o] = res.y;
        Ts[hid * 4 + 2][o] = res.z;
        Ts[hid * 4 + 3][o] = res.w;
    }
    __syncthreads();
    // split-bf16 transposed write: [hw][c32]
    {
        const int hw = tid >> 1, half = tid & 1;
        uint32_t hu[8], lu[8];
#pragma unroll
        for (int u = 0; u < 8; u++) {
            uint16_t h0, l0, h1, l1;
            split_bf16(Ts[hw][half * 16 + 2 * u], h0, l0);
            split_bf16(Ts[hw][half * 16 + 2 * u + 1], h1, l1);
            hu[u] = (uint32_t)h0 | ((uint32_t)h1 << 16);
            lu[u] = (uint32_t)l0 | ((uint32_t)l1 << 16);
        }
        __nv_bfloat16* ph = sel ? g_kh : g_qh;
        __nv_bfloat16* pl = sel ? g_kl : g_ql;
        size_t off = ((size_t)b * HW + hw0 + hw) * 32 + half * 16;
        *(uint4*)&ph[off]     = make_uint4(hu[0], hu[1], hu[2], hu[3]);
        *(uint4*)&ph[off + 8] = make_uint4(hu[4], hu[5], hu[6], hu[7]);
        *(uint4*)&pl[off]     = make_uint4(lu[0], lu[1], lu[2], lu[3]);
        *(uint4*)&pl[off + 8] = make_uint4(lu[4], lu[5], lu[6], lu[7]);
    }
}

// ===================== v projection: split-bf16 mma.sync ===================
__global__ __launch_bounds__(256) void v_mma(const float* __restrict__ X,
                                             const float* __restrict__ bias,
                                             float* __restrict__ vt) {
    extern __shared__ char dynsm[];
    const int tid  = threadIdx.x;
    const int lane = tid & 31;
    const int wid  = tid >> 5;
    const int wm   = wid & 3;
    const int wn   = wid >> 2;
    const int n0   = blockIdx.x * 128;
    const int m0   = blockIdx.y * 128;
    const int b    = blockIdx.z;

    const uint32_t smbase = smem_u32(dynsm);
    const uint32_t tBhi = smbase, tBlo = smbase + 16384;
    const uint32_t tAhi = smbase + 32768, tAlo = smbase + 49152;

    float acc[2][8][4];
#pragma unroll
    for (int mt = 0; mt < 2; mt++)
#pragma unroll
        for (int j = 0; j < 8; j++)
#pragma unroll
            for (int e = 0; e < 4; e++) acc[mt][j][e] = 0.f;

    const int arow  = wm * 32 + (lane & 15);
    const int acolh = (lane >> 4) * 16;
    const int brow  = wn * 64 + (lane & 7) + ((lane >> 4) << 3);
    const int bcolh = ((lane >> 3) & 1) * 16;
    const int c2    = tid >> 5;

    for (int s = 0; s < 4; s++) {
        const int kc = s * 64;
        __syncthreads();
#pragma unroll
        for (int i = 0; i < 8; i++) {
            const int t = i >> 2;
            const int c = ((i & 3) << 8) + tid;
            const int r = c >> 3, c16 = c & 7;
            uint32_t dst = (t ? tAlo : tAhi) + SWZ128((uint32_t)(r * 128 + c16 * 16));
            const __nv_bfloat16* src = (t ? g_Wvl : g_Wvh) + (size_t)(m0 + r) * 256 + kc + c16 * 8;
            CP_ASYNC16(dst, src);
        }
        CP_COMMIT();
#pragma unroll
        for (int cc = 0; cc < 4; cc++) {
            const int cp = c2 + 8 * cc;
            const size_t row0 = ((size_t)b * Cc + kc + 2 * cp) * HW + n0;
#pragma unroll
            for (int pb = 0; pb < 4; pb++) {
                const int px = lane + 32 * pb;
                float v0 = X[row0 + px];
                float v1 = X[row0 + HW + px];
                uint16_t h0, l0, h1, l1;
                split_bf16(v0, h0, l0);
                split_bf16(v1, h1, l1);
                uint32_t off = SWZ128((uint32_t)(px * 128 + cp * 4));
                *(uint32_t*)(dynsm + off)         = (uint32_t)h0 | ((uint32_t)h1 << 16);
                *(uint32_t*)(dynsm + 16384 + off) = (uint32_t)l0 | ((uint32_t)l1 << 16);
            }
        }
        CP_WAIT0();
        __syncthreads();

#pragma unroll
        for (int ks = 0; ks < 4; ks++) {
            uint32_t ah[2][4], al[2][4], bh[4][4], bl[4][4];
#pragma unroll
            for (int mt = 0; mt < 2; mt++) {
                uint32_t off = SWZ128((uint32_t)((arow + mt * 16) * 128 + ks * 32 + acolh));
                ldsm_x4(ah[mt], tAhi + off);
                ldsm_x4(al[mt], tAlo + off);
            }
#pragma unroll
            for (int j = 0; j < 4; j++) {
                uint32_t off = SWZ128((uint32_t)((brow + j * 16) * 128 + ks * 32 + bcolh));
                ldsm_x4(bh[j], tBhi + off);
                ldsm_x4(bl[j], tBlo + off);
            }
#pragma unroll
            for (int mt = 0; mt < 2; mt++)
#pragma unroll
                for (int j = 0; j < 4; j++) {
                    mma_bf16(acc[mt][2 * j],     ah[mt], bh[j][0], bh[j][1]);
                    mma_bf16(acc[mt][2 * j + 1], ah[mt], bh[j][2], bh[j][3]);
                    mma_bf16(acc[mt][2 * j],     al[mt], bh[j][0], bh[j][1]);
                    mma_bf16(acc[mt][2 * j + 1], al[mt], bh[j][2], bh[j][3]);
                    mma_bf16(acc[mt][2 * j],     ah[mt], bl[j][0], bl[j][1]);
                    mma_bf16(acc[mt][2 * j + 1], ah[mt], bl[j][2], bl[j][3]);
                }
        }
    }

    __syncthreads();
    float* smep = (float*)dynsm;
#pragma unroll
    for (int mt = 0; mt < 2; mt++) {
        const int o_lo = wm * 32 + mt * 16 + (lane >> 2);
        const int o_hi = o_lo + 8;
        const float bi_lo = bias[m0 + o_lo], bi_hi = bias[m0 + o_hi];
#pragma unroll
        for (int j = 0; j < 8; j++) {
            const int p = wn * 64 + j * 8 + 2 * (lane & 3);
            smep[p * 132 + o_lo]       = acc[mt][j][0] + bi_lo;
            smep[(p + 1) * 132 + o_lo] = acc[mt][j][1] + bi_lo;
            smep[p * 132 + o_hi]       = acc[mt][j][2] + bi_hi;
            smep[(p + 1) * 132 + o_hi] = acc[mt][j][3] + bi_hi;
        }
    }
    __syncthreads();
#pragma unroll
    for (int r = 0; r < 16; r++) {
        const int p = wid + 8 * r;
        float4 v = *(const float4*)&smep[p * 132 + lane * 4];
        *(float4*)&vt[((size_t)b * HW + n0 + p) * Cc + m0 + lane * 4] = v;
    }
}

// ===================== tensor-core energy top-2 + certified argmax =========
// CTA: 128 queries x all 4096 keys (32 key tiles). 8 warps = 4(key) x 2(query)
// smem: q 16KB | k 3x16KB | red 6KB
#define EM_K 16384
#define EM_RED (16384 + 49152)
#define EM_TOTAL (EM_RED + 6144)

__device__ __forceinline__ void em_stage_k(uint32_t smbase, int buf, int kt, int b) {
    const int tid = threadIdx.x;
#pragma unroll
    for (int i = 0; i < 4; i++) {
        int idx = tid + i * 256;                  // 0..1023
        int plane = idx >> 9;
        int r = (idx >> 2) & 127;
        int seg = idx & 3;
        const __nv_bfloat16* src = (plane ? g_kl : g_kh)
            + ((size_t)b * HW + kt * 128 + r) * 32 + seg * 8;
        uint32_t dst = smbase + EM_K + buf * 16384 + plane * 8192 + r * 64 + seg * 16;
        CP_ASYNC16(dst, src);
    }
    CP_COMMIT();
}

__global__ __launch_bounds__(256) void energy_mma() {
    extern __shared__ char dynsm[];
    const int tid  = threadIdx.x;
    const int lane = tid & 31;
    const int wid  = tid >> 5;
    const int wm   = wid & 3;
    const int wn   = wid >> 2;
    const int jt   = blockIdx.x;                 // 32 query tiles
    const int b    = blockIdx.y;

    const uint32_t smbase = smem_u32(dynsm);

    // stage q tile (once) + k tile 0 -> group0 ; k tile 1 -> group1
#pragma unroll
    for (int i = 0; i < 4; i++) {
        int idx = tid + i * 256;
        int plane = idx >> 9;
        int r = (idx >> 2) & 127;
        int seg = idx & 3;
        const __nv_bfloat16* src = (plane ? g_ql : g_qh)
            + ((size_t)b * HW + jt * 128 + r) * 32 + seg * 8;
        uint32_t dst = smbase + plane * 8192 + r * 64 + seg * 16;
        CP_ASYNC16(dst, src);
    }
    em_stage_k(smbase, 0, 0, b);                 // commits q + k0 as group0
    em_stage_k(smbase, 1, 1, b);                 // group1

    float v1[16], v2[16];
    int   i1[16];
#pragma unroll
    for (int qs = 0; qs < 16; qs++) { v1[qs] = -FLT_MAX; v2[qs] = -FLT_MAX; i1[qs] = 0; }

    const uint32_t offA0 = (uint32_t)((wm * 32 + (lane & 15)) * 64 + ((lane >> 4) << 4));
    const uint32_t offB0 = (uint32_t)((wn * 64 + (lane & 7) + ((lane >> 4) << 3)) * 64
                                      + (((lane >> 3) & 1) << 4));

    for (int kt = 0; kt < 32; kt++) {
        CP_WAIT1();
        __syncthreads();
        if (kt + 2 < 32) em_stage_k(smbase, (kt + 2) % 3, kt + 2, b);

        const uint32_t kb = smbase + EM_K + (kt % 3) * 16384;
        float acc[2][8][4];
#pragma unroll
        for (int mt = 0; mt < 2; mt++)
#pragma unroll
            for (int jj = 0; jj < 8; jj++)
#pragma unroll
                for (int e = 0; e < 4; e++) acc[mt][jj][e] = 0.f;

#pragma unroll
        for (int ks = 0; ks < 2; ks++) {
            uint32_t kh_[2][4], kl_[2][4], qh_[4][4], ql_[4][4];
#pragma unroll
            for (int mt = 0; mt < 2; mt++) {
                uint32_t off = offA0 + mt * 16 * 64 + ks * 32;
                ldsm_x4(kh_[mt], kb + off);
                ldsm_x4(kl_[mt], kb + 8192 + off);
            }
#pragma unroll
            for (int j = 0; j < 4; j++) {
                uint32_t off = offB0 + j * 16 * 64 + ks * 32;
                ldsm_x4(qh_[j], smbase + off);
                ldsm_x4(ql_[j], smbase + 8192 + off);
            }
#pragma unroll
            for (int mt = 0; mt < 2; mt++)
#pragma unroll
                for (int j = 0; j < 4; j++) {
                    mma_bf16(acc[mt][2 * j],     kh_[mt], qh_[j][0], qh_[j][1]);
                    mma_bf16(acc[mt][2 * j + 1], kh_[mt], qh_[j][2], qh_[j][3]);
                    mma_bf16(acc[mt][2 * j],     kh_[mt], ql_[j][0], ql_[j][1]);
                    mma_bf16(acc[mt][2 * j + 1], kh_[mt], ql_[j][2], ql_[j][3]);
                    mma_bf16(acc[mt][2 * j],     kl_[mt], qh_[j][0], qh_[j][1]);
                    mma_bf16(acc[mt][2 * j + 1], kl_[mt], qh_[j][2], qh_[j][3]);
                }
        }

        // top-2 update (branchy; common path 1 cmp)
        const int kbase = kt * 128 + wm * 32 + (lane >> 2);
#pragma unroll
        for (int mt = 0; mt < 2; mt++)
#pragma unroll
            for (int jj = 0; jj < 8; jj++)
#pragma unroll
                for (int e = 0; e < 4; e++) {
                    const float v = acc[mt][jj][e];
                    const int qs = jj * 2 + (e & 1);
                    if (v > v2[qs]) {
                        const int key = kbase + mt * 16 + ((e >> 1) << 3);
                        if (v > v1[qs]) { v2[qs] = v1[qs]; v1[qs] = v; i1[qs] = key; }
                        else v2[qs] = v;
                    }
                }
        __syncthreads();
    }

    // in-warp reduce across the 8 threads sharing each query column
#pragma unroll
    for (int qs = 0; qs < 16; qs++) {
#pragma unroll
        for (int st = 4; st <= 16; st <<= 1) {
            float ov1 = __shfl_xor_sync(0xffffffff, v1[qs], st);
            float ov2 = __shfl_xor_sync(0xffffffff, v2[qs], st);
            int   oi1 = __shfl_xor_sync(0xffffffff, i1[qs], st);
            float nv2 = fmaxf(fminf(v1[qs], ov1), fmaxf(v2[qs], ov2));
            if (ov1 > v1[qs]) { v1[qs] = ov1; i1[qs] = oi1; }
            v2[qs] = nv2;
        }
    }
    // lanes 0-3 publish per (wn, col, wm)
    float* red = (float*)(dynsm + EM_RED);
    if (lane < 4) {
#pragma unroll
        for (int qs = 0; qs < 16; qs++) {
            const int col = (qs >> 1) * 8 + 2 * lane + (qs & 1);
            float* rp = red + ((wn * 64 + col) * 4 + wm) * 3;
            rp[0] = v1[qs];
            rp[1] = __int_as_float(i1[qs]);
            rp[2] = v2[qs];
        }
    }
    __syncthreads();
    if (tid < 128) {
        float* rp = red + tid * 12;
        float V1 = rp[0], V2 = rp[2];
        int   I1 = __float_as_int(rp[1]);
#pragma unroll
        for (int w = 1; w < 4; w++) {
            float a1 = rp[w * 3], a2 = rp[w * 3 + 2];
            int   ai = __float_as_int(rp[w * 3 + 1]);
            float nv2 = fmaxf(fminf(V1, a1), fmaxf(V2, a2));
            if (a1 > V1) { V1 = a1; I1 = ai; }
            V2 = nv2;
        }
        const int jq = jt * 128 + tid;
        g_S[(size_t)b * HW + jq]    = V1;
        g_arg[(size_t)b * HW + jq]  = I1;
        g_flag[(size_t)b * HW + jq] = (V1 - V2 < 4e-3f) ? 1 : 0;
    }
}

// exact fp32 recheck for flagged queries (one warp per query, early exit)
__global__ __launch_bounds__(128) void recheck() {
    const int b = blockIdx.y;
    const int j = blockIdx.x * 4 + (threadIdx.x >> 5);
    if (!g_flag[(size_t)b * HW + j]) return;
    const int lane = threadIdx.x & 31;

    float qv[32];
#pragma unroll
    for (int c = 0; c < 32; c++) qv[c] = g_q[((size_t)b * C8 + c) * HW + j];

    float best = -FLT_MAX;
    int   bi = 0;
    for (int i = lane; i < HW; i += 32) {
        float e = 0.f;
#pragma unroll
        for (int c = 0; c < 32; c++) e = fmaf(g_k[((size_t)b * C8 + c) * HW + i], qv[c], e);
        if (e > best) { best = e; bi = i; }    // ascending i -> first max per lane
    }
#pragma unroll
    for (int st = 16; st; st >>= 1) {
        float ov = __shfl_xor_sync(0xffffffff, best, st);
        int   oi = __shfl_xor_sync(0xffffffff, bi, st);
        if (ov > best || (ov == best && oi < bi)) { best = ov; bi = oi; }
    }
    if (lane == 0) {
        g_S[(size_t)b * HW + j]   = best;
        g_arg[(size_t)b * HW + j] = bi;
    }
}

// ===================== conv input prep =====================================
__global__ void zero_halo() {
    const int t = blockIdx.x * 256 + threadIdx.x;
    if (t >= Bb * 260 * 64) return;
    const int u = t & 63;
    const int pix = (t >> 6) % 260;
    const int b = t / (260 * 64);
    int y, x;
    if (pix < 66)       { y = 0;        x = pix; }
    else if (pix < 132) { y = 65;       x = pix - 66; }
    else if (pix < 196) { y = pix - 131; x = 0; }
    else                { y = pix - 195; x = 65; }
    ((uint4*)g_Xt)[(((size_t)(b * 66 + y) * 66 + x) << 7) + u] = make_uint4(0, 0, 0, 0);
}

__global__ __launch_bounds__(256) void fill_xt(const float* __restrict__ front_x) {
    __shared__ float sm[32][65];
    const int c0 = blockIdx.x * 32;
    const int y  = blockIdx.y;
    const int b  = blockIdx.z;
    const int tid = threadIdx.x;
    const int x  = tid >> 2;
    const int g  = tid & 3;

    float vals[8];
    if (c0 < 256) {
#pragma unroll
        for (int pass = 0; pass < 8; pass++) {
            int idx = tid + pass * 256;
            int cc = idx >> 6, xx = idx & 63;
            sm[cc][xx] = front_x[((size_t)b * Cc + c0 + cc) * HW + y * Ww + xx];
        }
        __syncthreads();
#pragma unroll
        for (int e = 0; e < 8; e++) vals[e] = sm[g * 8 + e][x];
    } else {
        const int a = g_arg[b * HW + y * Ww + x];
        const float* vp = g_vt + ((size_t)b * HW + a) * Cc + (c0 - 256) + g * 8;
        float4 u0 = *(const float4*)vp;
        float4 u1 = *(const float4*)(vp + 4);
        vals[0] = u0.x; vals[1] = u0.y; vals[2] = u0.z; vals[3] = u0.w;
        vals[4] = u1.x; vals[5] = u1.y; vals[6] = u1.z; vals[7] = u1.w;
    }

    uint32_t hu[4], lu[4];
#pragma unroll
    for (int e = 0; e < 4; e++) {
        uint16_t h0, l0, h1, l1;
        split_bf16(vals[e * 2], h0, l0);
        split_bf16(vals[e * 2 + 1], h1, l1);
        hu[e] = (uint32_t)h0 | ((uint32_t)h1 << 16);
        lu[e] = (uint32_t)l0 | ((uint32_t)l1 << 16);
    }
    size_t base = ((size_t)(b * 66 + y + 1) * 66 + (x + 1)) * 1024 + c0 + g * 8;
    *(uint4*)&g_Xt[base]       = make_uint4(hu[0], hu[1], hu[2], hu[3]);
    *(uint4*)&g_Xt[base + 512] = make_uint4(lu[0], lu[1], lu[2], lu[3]);
}

__global__ void prep_w(const float* __restrict__ Wf) {
    int t = blockIdx.x * 256 + threadIdx.x;
    int o = t >> 9, i = t & 511;
#pragma unroll
    for (int k = 0; k < 9; k++) {
        float w = Wf[((size_t)o * 512 + i) * 9 + k];
        uint16_t h, l;
        split_bf16(w, h, l);
        g_Wa[(((size_t)0 * 9 + k) * 256 + o) * 512 + i] = __ushort_as_bfloat16(h);
        g_Wa[(((size_t)1 * 9 + k) * 256 + o) * 512 + i] = __ushort_as_bfloat16(l);
    }
}

__global__ void prep_wv(const float* __restrict__ Wv) {
    int t = blockIdx.x * 256 + threadIdx.x;
    uint16_t h, l;
    split_bf16(Wv[t], h, l);
    g_Wvh[t] = __ushort_as_bfloat16(h);
    g_Wvl[t] = __ushort_as_bfloat16(l);
}

// ===================== mma.sync conv3x3 + fused epilogue ====================
#define STAGE 65536
#define NCHUNK 72

__device__ __forceinline__ void stage_chunk(uint32_t stg, int s, int b, int y0, int m0) {
    const int tap = s >> 3, kc = (s & 7) * 64;
    const int dy = tap / 3, dx = tap % 3;
    const int tid = threadIdx.x;
#pragma unroll
    for (int i = 0; i < 16; i++) {
        const int t = i >> 2;
        const int c = ((i & 3) << 8) + tid;
        const int r = c >> 3, c16 = c & 7;
        uint32_t dst = stg + (uint32_t)(t * 16384) + SWZ128((uint32_t)(r * 128 + c16 * 16));
        const void* src;
        if (t < 2) {
            const int ry = r >> 6, x = r & 63;
            src = &g_Xt[(((size_t)(b * 66 + y0 + ry + dy) * 66) + (x + dx)) * 1024
                        + t * 512 + kc + c16 * 8];
        } else {
            src = &g_Wa[(((size_t)((t - 2) * 9 + tap) * 256) + m0 + r) * 512 + kc + c16 * 8];
        }
        CP_ASYNC16(dst, src);
    }
    CP_COMMIT();
}

__global__ __launch_bounds__(256, 1) void conv_mma(const float* __restrict__ front_x,
                                                   const float* __restrict__ bf,
                                                   float* __restrict__ out) {
    extern __shared__ char dynsm[];
    const int tid  = threadIdx.x;
    const int lane = tid & 31;
    const int wid  = tid >> 5;
    const int wm   = wid & 3;
    const int wn   = wid >> 2;
    const int nt   = blockIdx.x;
    const int m0   = blockIdx.y * 128;
    const int b    = blockIdx.z;
    const int y0   = nt * 2;
    const int n0   = nt * 128;

    const uint32_t smbase = smem_u32(dynsm);

    float acc[2][8][4];
#pragma unroll
    for (int mt = 0; mt < 2; mt++)
#pragma unroll
        for (int j = 0; j < 8; j++)
#pragma unroll
            for (int e = 0; e < 4; e++) acc[mt][j][e] = 0.f;

    const int arow  = wm * 32 + (lane & 15);
    const int acolh = (lane >> 4) * 16;
    const int brow  = wn * 64 + (lane & 7) + ((lane >> 4) << 3);
    const int bcolh = ((lane >> 3) & 1) * 16;

    stage_chunk(smbase, 0, b, y0, m0);
    stage_chunk(smbase + STAGE, 1, b, y0, m0);

    for (int s = 0; s < NCHUNK; s++) {
        CP_WAIT1();
        __syncthreads();
        if (s + 2 < NCHUNK)
            stage_chunk(smbase + ((s + 2) % 3) * STAGE, s + 2, b, y0, m0);

        const uint32_t base = smbase + (s % 3) * STAGE;
        const uint32_t tBhi = base, tBlo = base + 16384;
        const uint32_t tAhi = base + 32768, tAlo = base + 49152;

#pragma unroll
        for (int ks = 0; ks < 4; ks++) {
            uint32_t ah[2][4], al[2][4], bh[4][4], bl[4][4];
#pragma unroll
            for (int mt = 0; mt < 2; mt++) {
                uint32_t off = SWZ128((uint32_t)((arow + mt * 16) * 128 + ks * 32 + acolh));
                ldsm_x4(ah[mt], tAhi + off);
                ldsm_x4(al[mt], tAlo + off);
            }
#pragma unroll
            for (int j = 0; j < 4; j++) {
                uint32_t off = SWZ128((uint32_t)((brow + j * 16) * 128 + ks * 32 + bcolh));
                ldsm_x4(bh[j], tBhi + off);
                ldsm_x4(bl[j], tBlo + off);
            }
#pragma unroll
            for (int mt = 0; mt < 2; mt++)
#pragma unroll
                for (int j = 0; j < 4; j++) {
                    mma_bf16(acc[mt][2 * j],     ah[mt], bh[j][0], bh[j][1]);
                    mma_bf16(acc[mt][2 * j + 1], ah[mt], bh[j][2], bh[j][3]);
                    mma_bf16(acc[mt][2 * j],     al[mt], bh[j][0], bh[j][1]);
                    mma_bf16(acc[mt][2 * j + 1], al[mt], bh[j][2], bh[j][3]);
                    mma_bf16(acc[mt][2 * j],     ah[mt], bl[j][0], bl[j][1]);
                    mma_bf16(acc[mt][2 * j + 1], ah[mt], bl[j][2], bl[j][3]);
                }
        }
        __syncthreads();
    }

    const float* Sb = g_S + (size_t)b * HW;
#pragma unroll
    for (int mt = 0; mt < 2; mt++) {
        const int o_lo = m0 + wm * 32 + mt * 16 + (lane >> 2);
        const int o_hi = o_lo + 8;
        const float bi_lo = bf[o_lo], bi_hi = bf[o_hi];
#pragma unroll
        for (int j = 0; j < 8; j++) {
            const int p = n0 + wn * 64 + j * 8 + 2 * (lane & 3);
            const float2 Sv = *(const float2*)&Sb[p];
            const size_t off0 = ((size_t)(b * Cc + o_lo)) * HW + p;
            const size_t off1 = ((size_t)(b * Cc + o_hi)) * HW + p;
            const float2 f0 = *(const float2*)&front_x[off0];
            const float2 f1 = *(const float2*)&front_x[off1];
            float2 r0, r1;
            r0.x = f0.x + (acc[mt][j][0] + bi_lo) * Sv.x;
            r0.y = f0.y + (acc[mt][j][1] + bi_lo) * Sv.y;
            r1.x = f1.x + (acc[mt][j][2] + bi_hi) * Sv.x;
            r1.y = f1.y + (acc[mt][j][3] + bi_hi) * Sv.y;
            *(float2*)&out[off0] = r0;
            *(float2*)&out[off1] = r1;
        }
    }
}

// ===================== launch ==============================================
extern "C" void kernel_launch(void* const* d_in, const int* in_sizes, int n_in,
                              void* d_out, int out_size) {
    const float* front_x     = (const float*)d_in[0];
    const float* cross_x     = (const float*)d_in[1];
    const float* front_x_hat = (const float*)d_in[2];
    const float* Wq = (const float*)d_in[3];
    const float* bq = (const float*)d_in[4];
    const float* Wk = (const float*)d_in[5];
    const float* bk = (const float*)d_in[6];
    const float* Wv = (const float*)d_in[7];
    const float* bv = (const float*)d_in[8];
    const float* Wf = (const float*)d_in[9];
    const float* bf = (const float*)d_in[10];
    float* out = (float*)d_out;

    cudaFuncSetAttribute(conv_mma, cudaFuncAttributeMaxDynamicSharedMemorySize, 3 * STAGE);
    cudaFuncSetAttribute(v_mma, cudaFuncAttributeMaxDynamicSharedMemorySize, 128 * 132 * 4);
    cudaFuncSetAttribute(energy_mma, cudaFuncAttributeMaxDynamicSharedMemorySize, EM_TOTAL);

    float* vt;
    cudaGetSymbolAddress((void**)&vt, g_vt);

    zero_halo<<<260, 256>>>();
    prep_w<<<512, 256>>>(Wf);
    prep_wv<<<256, 256>>>(Wv);

    gemm_qk<<<dim3(32, 2, 4), 256>>>(cross_x, front_x, Wq, bq, Wk, bk);
    v_mma<<<dim3(32, 2, 4), 256, 128 * 132 * 4>>>(front_x_hat, bv, vt);

    energy_mma<<<dim3(32, 4), 256, EM_TOTAL>>>();
    recheck<<<dim3(1024, 4), 128>>>();

    fill_xt<<<dim3(16, 64, 4), 256>>>(front_x);

    conv_mma<<<dim3(32, 2, 4), 256, 3 * STAGE>>>(front_x, bf, out);
}

// round 9
// speedup vs baseline: 1.5428x; 1.5428x over previous
#include <cuda_runtime.h>
#include <cuda_fp16.h>
#include <float.h>
#include <stdint.h>

#define Bb 4
#define Cc 256
#define C8 32
#define Hh 64
#define Ww 64
#define HW 4096

// ===================== helpers =============================================
__device__ __forceinline__ uint32_t smem_u32(const void* p) {
    uint32_t a;
    asm("{ .reg .u64 t; cvta.to.shared.u64 t, %1; cvt.u32.u64 %0, t; }"
        : "=r"(a) : "l"(p));
    return a;
}
#define SWZ128(off) ((off) ^ (((off) >> 3) & 0x70))

__device__ __forceinline__ void ldsm_x4(uint32_t (&r)[4], uint32_t addr) {
    asm volatile("ldmatrix.sync.aligned.m8n8.x4.shared.b16 {%0,%1,%2,%3}, [%4];"
                 : "=r"(r[0]), "=r"(r[1]), "=r"(r[2]), "=r"(r[3]) : "r"(addr));
}

__device__ __forceinline__ void mma_f16(float (&d)[4], const uint32_t (&a)[4],
                                        uint32_t b0, uint32_t b1) {
    asm volatile(
        "mma.sync.aligned.m16n8k16.row.col.f32.f16.f16.f32 "
        "{%0,%1,%2,%3}, {%4,%5,%6,%7}, {%8,%9}, {%0,%1,%2,%3};"
        : "+f"(d[0]), "+f"(d[1]), "+f"(d[2]), "+f"(d[3])
        : "r"(a[0]), "r"(a[1]), "r"(a[2]), "r"(a[3]), "r"(b0), "r"(b1));
}

#define CP_ASYNC16(dst, src) \
    asm volatile("cp.async.cg.shared.global [%0], [%1], 16;" :: "r"(dst), "l"(src) : "memory")
#define CP_COMMIT()  asm volatile("cp.async.commit_group;" ::: "memory")
#define CP_WAIT2()   asm volatile("cp.async.wait_group 2;" ::: "memory")
#define CP_WAIT0()   asm volatile("cp.async.wait_group 0;" ::: "memory")

__device__ __forceinline__ uint32_t pack_h2(float a, float b) {
    __half2 h = __floats2half2_rn(a, b);
    return *(uint32_t*)&h;
}

// ===================== scratch =============================================
__device__ float g_q[Bb * C8 * HW];
__device__ float g_k[Bb * C8 * HW];
__device__ float g_vt[Bb * HW * Cc];          // NHWC value: [b][p][c]
__device__ float g_pmax[Bb * 4 * HW];
__device__ int   g_parg[Bb * 4 * HW];
__device__ float g_S[Bb * HW];
__device__ int   g_arg[Bb * HW];
// NHWC fp16 single plane, zero halo (device globals zero-init; halo never written)
__device__ __half g_Xt[(size_t)Bb * 66 * 66 * 512];
// conv weights split fp16: [seg(hi0/lo1)][tap9][o 256][c 512]
__device__ __half g_Wa[2 * 9 * 256 * 512];
// v weights split fp16: [o 256][c 256]
__device__ __half g_Wvh[256 * 256];
__device__ __half g_Wvl[256 * 256];

// ===================== fused q+k projection (exact fp32) ====================
__global__ __launch_bounds__(256) void gemm_qk(const float* __restrict__ cross_x,
                                               const float* __restrict__ front_x,
                                               const float* __restrict__ Wq,
                                               const float* __restrict__ bq,
                                               const float* __restrict__ Wk,
                                               const float* __restrict__ bk) {
    __shared__ float Xs[16][128];
    __shared__ float Ws[16][36];
    const int b   = blockIdx.z;
    const int sel = blockIdx.y;                 // 0 -> q, 1 -> k
    const int hw0 = blockIdx.x * 128;
    const int tid = threadIdx.x;
    const int hid = tid & 31;
    const int oid = tid >> 5;

    const float* X    = sel ? front_x : cross_x;
    const float* Wm   = sel ? Wk : Wq;
    const float* bias = sel ? bk : bq;
    float*       out  = sel ? g_k : g_q;

    const float* xb = X + (size_t)b * Cc * HW;
    float acc[4][4];
#pragma unroll
    for (int n = 0; n < 4; n++)
#pragma unroll
        for (int m = 0; m < 4; m++) acc[n][m] = 0.f;

    for (int c0 = 0; c0 < Cc; c0 += 16) {
        __syncthreads();
#pragma unroll
        for (int r = 0; r < 8; r++) {
            int idx = tid + r * 256;
            int cc = idx >> 7, h = idx & 127;
            Xs[cc][h] = xb[(size_t)(c0 + cc) * HW + hw0 + h];
        }
#pragma unroll
        for (int r = 0; r < 2; r++) {
            int idx = tid + r * 256;
            int cc = idx >> 5, o = idx & 31;
            Ws[cc][o] = Wm[(size_t)o * Cc + c0 + cc];
        }
        __syncthreads();
#pragma unroll
        for (int cc = 0; cc < 16; cc++) {
            float4 wv = *(const float4*)&Ws[cc][oid * 4];
            float4 xv = *(const float4*)&Xs[cc][hid * 4];
            float wa[4] = {wv.x, wv.y, wv.z, wv.w};
            float xa[4] = {xv.x, xv.y, xv.z, xv.w};
#pragma unroll
            for (int n = 0; n < 4; n++)
#pragma unroll
                for (int m = 0; m < 4; m++) acc[n][m] += wa[n] * xa[m];
        }
    }
#pragma unroll
    for (int n = 0; n < 4; n++) {
        int o = oid * 4 + n;
        float bi = bias[o];
        float4 res;
        res.x = acc[n][0] + bi;
        res.y = acc[n][1] + bi;
        res.z = acc[n][2] + bi;
        res.w = acc[n][3] + bi;
        *(float4*)&out[(size_t)b * C8 * HW + (size_t)o * HW + hw0 + hid * 4] = res;
    }
}

// ===================== v projection: fp16 2-term mma.sync ===================
// D[128 o][128 px] per CTA; K=256 in 4 chunks of 64. A = Wv hi/lo planes
// (cp.async), B = front_x_hat LDG fp32 -> fp16 -> STS ([px][ch] SW128).
__global__ __launch_bounds__(256) void v_mma(const float* __restrict__ X,
                                             const float* __restrict__ bias,
                                             float* __restrict__ vt) {
    extern __shared__ char dynsm[];
    const int tid  = threadIdx.x;
    const int lane = tid & 31;
    const int wid  = tid >> 5;
    const int wm   = wid & 3;
    const int wn   = wid >> 2;
    const int n0   = blockIdx.x * 128;
    const int m0   = blockIdx.y * 128;
    const int b    = blockIdx.z;

    const uint32_t smbase = smem_u32(dynsm);
    const uint32_t tB  = smbase;
    const uint32_t tAh = smbase + 16384;
    const uint32_t tAl = smbase + 32768;

    float acc[2][8][4];
#pragma unroll
    for (int mt = 0; mt < 2; mt++)
#pragma unroll
        for (int j = 0; j < 8; j++)
#pragma unroll
            for (int e = 0; e < 4; e++) acc[mt][j][e] = 0.f;

    const int arow  = wm * 32 + (lane & 15);
    const int acolh = (lane >> 4) * 16;
    const int brow  = wn * 64 + (lane & 7) + ((lane >> 4) << 3);
    const int bcolh = ((lane >> 3) & 1) * 16;
    const int c2    = tid >> 5;

    for (int s = 0; s < 4; s++) {
        const int kc = s * 64;
        __syncthreads();
        // A tiles (Wv hi/lo) via cp.async: 2 x 16KB
#pragma unroll
        for (int i = 0; i < 8; i++) {
            const int t = i >> 2;
            const int c = ((i & 3) << 8) + tid;
            const int r = c >> 3, c16 = c & 7;
            uint32_t dst = (t ? tAl : tAh) + SWZ128((uint32_t)(r * 128 + c16 * 16));
            const __half* src = (t ? g_Wvl : g_Wvh) + (size_t)(m0 + r) * 256 + kc + c16 * 8;
            CP_ASYNC16(dst, src);
        }
        CP_COMMIT();
        // B tile: LDG fp32 -> fp16 -> STS [px][ch]
#pragma unroll
        for (int cc = 0; cc < 4; cc++) {
            const int cp = c2 + 8 * cc;
            const size_t row0 = ((size_t)b * Cc + kc + 2 * cp) * HW + n0;
#pragma unroll
            for (int pb = 0; pb < 4; pb++) {
                const int px = lane + 32 * pb;
                float v0 = X[row0 + px];
                float v1 = X[row0 + HW + px];
                uint32_t off = SWZ128((uint32_t)(px * 128 + cp * 4));
                *(uint32_t*)(dynsm + off) = pack_h2(v0, v1);
            }
        }
        CP_WAIT0();
        __syncthreads();

#pragma unroll
        for (int ks = 0; ks < 4; ks++) {
            uint32_t ah[2][4], al[2][4], bx[4][4];
#pragma unroll
            for (int mt = 0; mt < 2; mt++) {
                uint32_t off = SWZ128((uint32_t)((arow + mt * 16) * 128 + ks * 32 + acolh));
                ldsm_x4(ah[mt], tAh + off);
                ldsm_x4(al[mt], tAl + off);
            }
#pragma unroll
            for (int j = 0; j < 4; j++) {
                uint32_t off = SWZ128((uint32_t)((brow + j * 16) * 128 + ks * 32 + bcolh));
                ldsm_x4(bx[j], tB + off);
            }
#pragma unroll
            for (int mt = 0; mt < 2; mt++)
#pragma unroll
                for (int j = 0; j < 4; j++) {
                    mma_f16(acc[mt][2 * j],     ah[mt], bx[j][0], bx[j][1]);
                    mma_f16(acc[mt][2 * j + 1], ah[mt], bx[j][2], bx[j][3]);
                    mma_f16(acc[mt][2 * j],     al[mt], bx[j][0], bx[j][1]);
                    mma_f16(acc[mt][2 * j + 1], al[mt], bx[j][2], bx[j][3]);
                }
        }
    }

    // epilogue: transpose through padded smem (row stride 132 floats)
    __syncthreads();
    float* smep = (float*)dynsm;
#pragma unroll
    for (int mt = 0; mt < 2; mt++) {
        const int o_lo = wm * 32 + mt * 16 + (lane >> 2);
        const int o_hi = o_lo + 8;
        const float bi_lo = bias[m0 + o_lo], bi_hi = bias[m0 + o_hi];
#pragma unroll
        for (int j = 0; j < 8; j++) {
            const int p = wn * 64 + j * 8 + 2 * (lane & 3);
            smep[p * 132 + o_lo]       = acc[mt][j][0] + bi_lo;
            smep[(p + 1) * 132 + o_lo] = acc[mt][j][1] + bi_lo;
            smep[p * 132 + o_hi]       = acc[mt][j][2] + bi_hi;
            smep[(p + 1) * 132 + o_hi] = acc[mt][j][3] + bi_hi;
        }
    }
    __syncthreads();
#pragma unroll
    for (int r = 0; r < 16; r++) {
        const int p = wid + 8 * r;
        float4 v = *(const float4*)&smep[p * 132 + lane * 4];
        *(float4*)&vt[((size_t)b * HW + n0 + p) * Cc + m0 + lane * 4] = v;
    }
}

// ===================== energy rowmax/argmax (exact fp32) ====================
__global__ __launch_bounds__(128) void energy_argmax() {
    __shared__ float ks[32][128];
    const int b  = blockIdx.y;
    const int j  = blockIdx.x * 128 + threadIdx.x;
    const int sp = blockIdx.z;
    const float* qb = g_q + (size_t)b * C8 * HW;
    const float* kb = g_k + (size_t)b * C8 * HW;

    float qr[32];
#pragma unroll
    for (int c = 0; c < 32; c++) qr[c] = qb[c * HW + j];

    float best = -FLT_MAX;
    int   barg = 0;
    const int i0base = sp * 1024;

    for (int it = 0; it < 8; it++) {
        int i0 = i0base + it * 128;
        __syncthreads();
#pragma unroll
        for (int c = 0; c < 32; c++) ks[c][threadIdx.x] = kb[c * HW + i0 + threadIdx.x];
        __syncthreads();
#pragma unroll 4
        for (int ii = 0; ii < 128; ii += 4) {
            float a0 = 0.f, a1 = 0.f, a2 = 0.f, a3 = 0.f;
#pragma unroll
            for (int c = 0; c < 32; c++) {
                float4 kv = *(const float4*)&ks[c][ii];
                a0 += kv.x * qr[c];
                a1 += kv.y * qr[c];
                a2 += kv.z * qr[c];
                a3 += kv.w * qr[c];
            }
            if (a0 > best) { best = a0; barg = i0 + ii; }
            if (a1 > best) { best = a1; barg = i0 + ii + 1; }
            if (a2 > best) { best = a2; barg = i0 + ii + 2; }
            if (a3 > best) { best = a3; barg = i0 + ii + 3; }
        }
    }
    g_pmax[((size_t)b * 4 + sp) * HW + j] = best;
    g_parg[((size_t)b * 4 + sp) * HW + j] = barg;
}

__global__ void reduce_argmax() {
    int t = blockIdx.x * 256 + threadIdx.x;
    if (t >= Bb * HW) return;
    int b = t >> 12, j = t & 4095;
    float best = g_pmax[((size_t)b * 4) * HW + j];
    int   arg  = g_parg[((size_t)b * 4) * HW + j];
#pragma unroll
    for (int sp = 1; sp < 4; sp++) {
        float e = g_pmax[((size_t)b * 4 + sp) * HW + j];
        if (e > best) { best = e; arg = g_parg[((size_t)b * 4 + sp) * HW + j]; }
    }
    g_S[t] = best;
    g_arg[t] = arg;
}

// ===================== conv input prep (fp16, single plane) =================
__global__ __launch_bounds__(256) void fill_xt(const float* __restrict__ front_x) {
    __shared__ float sm[32][65];
    const int c0 = blockIdx.x * 32;
    const int y  = blockIdx.y;
    const int b  = blockIdx.z;
    const int tid = threadIdx.x;
    const int x  = tid >> 2;
    const int g  = tid & 3;

    float vals[8];
    if (c0 < 256) {
#pragma unroll
        for (int pass = 0; pass < 8; pass++) {
            int idx = tid + pass * 256;
            int cc = idx >> 6, xx = idx & 63;
            sm[cc][xx] = front_x[((size_t)b * Cc + c0 + cc) * HW + y * Ww + xx];
        }
        __syncthreads();
#pragma unroll
        for (int e = 0; e < 8; e++) vals[e] = sm[g * 8 + e][x];
    } else {
        const int a = g_arg[b * HW + y * Ww + x];
        const float* vp = g_vt + ((size_t)b * HW + a) * Cc + (c0 - 256) + g * 8;
        float4 u0 = *(const float4*)vp;
        float4 u1 = *(const float4*)(vp + 4);
        vals[0] = u0.x; vals[1] = u0.y; vals[2] = u0.z; vals[3] = u0.w;
        vals[4] = u1.x; vals[5] = u1.y; vals[6] = u1.z; vals[7] = u1.w;
    }

    uint32_t hu[4];
#pragma unroll
    for (int e = 0; e < 4; e++) hu[e] = pack_h2(vals[e * 2], vals[e * 2 + 1]);
    size_t base = ((size_t)(b * 66 + y + 1) * 66 + (x + 1)) * 512 + c0 + g * 8;
    *(uint4*)&g_Xt[base] = make_uint4(hu[0], hu[1], hu[2], hu[3]);
}

// conv weights: Wf(O=256, I=512, 3,3) -> g_Wa[seg][tap][o][i] fp16 hi/lo
__global__ void prep_w(const float* __restrict__ Wf) {
    int t = blockIdx.x * 256 + threadIdx.x;
    int o = t >> 9, i = t & 511;
#pragma unroll
    for (int k = 0; k < 9; k++) {
        float w = Wf[((size_t)o * 512 + i) * 9 + k];
        __half h = __float2half_rn(w);
        __half l = __float2half_rn(w - __half2float(h));
        g_Wa[(((size_t)0 * 9 + k) * 256 + o) * 512 + i] = h;
        g_Wa[(((size_t)1 * 9 + k) * 256 + o) * 512 + i] = l;
    }
}

__global__ void prep_wv(const float* __restrict__ Wv) {
    int t = blockIdx.x * 256 + threadIdx.x;
    float w = Wv[t];
    __half h = __float2half_rn(w);
    __half l = __float2half_rn(w - __half2float(h));
    g_Wvh[t] = h;
    g_Wvl[t] = l;
}

// ===================== mma.sync conv3x3 (fp16 2-term) + fused epilogue ======
// CTA: M=128 out-ch x N=128 px. K: 9 taps x 8 chunks of 64ch.
// Stage/chunk: 3 SW128 tiles of 128x64 fp16 (X, Wh, Wl; 16KB each),
// cp.async 4-stage pipeline (48KB/stage).
#define STAGE 49152
#define NCHUNK 72

__device__ __forceinline__ void stage_chunk(uint32_t stg, int s, int b, int y0, int m0) {
    const int tap = s >> 3, kc = (s & 7) * 64;
    const int dy = tap / 3, dx = tap % 3;
    const int tid = threadIdx.x;
#pragma unroll
    for (int i = 0; i < 12; i++) {
        const int t = i >> 2;                          // 0:X 1:Wh 2:Wl
        const int u = ((i & 3) << 8) + tid;            // 0..1023
        const int r = u >> 3, c16 = u & 7;
        uint32_t dst = stg + (uint32_t)(t * 16384) + SWZ128((uint32_t)(r * 128 + c16 * 16));
        const void* src;
        if (t == 0) {
            const int ry = r >> 6, x = r & 63;
            src = &g_Xt[(((size_t)(b * 66 + y0 + ry + dy) * 66) + (x + dx)) * 512
                        + kc + c16 * 8];
        } else {
            src = &g_Wa[(((size_t)((t - 1) * 9 + tap) * 256) + m0 + r) * 512 + kc + c16 * 8];
        }
        CP_ASYNC16(dst, src);
    }
    CP_COMMIT();
}

__global__ __launch_bounds__(256, 1) void conv_mma(const float* __restrict__ front_x,
                                                   const float* __restrict__ bf,
                                                   float* __restrict__ out) {
    extern __shared__ char dynsm[];
    const int tid  = threadIdx.x;
    const int lane = tid & 31;
    const int wid  = tid >> 5;
    const int wm   = wid & 3;
    const int wn   = wid >> 2;
    const int nt   = blockIdx.x;
    const int m0   = blockIdx.y * 128;
    const int b    = blockIdx.z;
    const int y0   = nt * 2;
    const int n0   = nt * 128;

    const uint32_t smbase = smem_u32(dynsm);

    float acc[2][8][4];
#pragma unroll
    for (int mt = 0; mt < 2; mt++)
#pragma unroll
        for (int j = 0; j < 8; j++)
#pragma unroll
            for (int e = 0; e < 4; e++) acc[mt][j][e] = 0.f;

    const int arow  = wm * 32 + (lane & 15);
    const int acolh = (lane >> 4) * 16;
    const int brow  = wn * 64 + (lane & 7) + ((lane >> 4) << 3);
    const int bcolh = ((lane >> 3) & 1) * 16;

    stage_chunk(smbase,             0, b, y0, m0);
    stage_chunk(smbase + STAGE,     1, b, y0, m0);
    stage_chunk(smbase + 2 * STAGE, 2, b, y0, m0);

    for (int s = 0; s < NCHUNK; s++) {
        CP_WAIT2();
        __syncthreads();
        if (s + 3 < NCHUNK)
            stage_chunk(smbase + ((s + 3) & 3) * STAGE, s + 3, b, y0, m0);

        const uint32_t base = smbase + (s & 3) * STAGE;
        const uint32_t tB  = base;
        const uint32_t tAh = base + 16384;
        const uint32_t tAl = base + 32768;

#pragma unroll
        for (int ks = 0; ks < 4; ks++) {
            uint32_t ah[2][4], al[2][4], bx[4][4];
#pragma unroll
            for (int mt = 0; mt < 2; mt++) {
                uint32_t off = SWZ128((uint32_t)((arow + mt * 16) * 128 + ks * 32 + acolh));
                ldsm_x4(ah[mt], tAh + off);
                ldsm_x4(al[mt], tAl + off);
            }
#pragma unroll
            for (int j = 0; j < 4; j++) {
                uint32_t off = SWZ128((uint32_t)((brow + j * 16) * 128 + ks * 32 + bcolh));
                ldsm_x4(bx[j], tB + off);
            }
#pragma unroll
            for (int mt = 0; mt < 2; mt++)
#pragma unroll
                for (int j = 0; j < 4; j++) {
                    mma_f16(acc[mt][2 * j],     ah[mt], bx[j][0], bx[j][1]);
                    mma_f16(acc[mt][2 * j + 1], ah[mt], bx[j][2], bx[j][3]);
                    mma_f16(acc[mt][2 * j],     al[mt], bx[j][0], bx[j][1]);
                    mma_f16(acc[mt][2 * j + 1], al[mt], bx[j][2], bx[j][3]);
                }
        }
        __syncthreads();
    }

    // fused epilogue: out = front_x + (conv + bf) * S
    const float* Sb = g_S + (size_t)b * HW;
#pragma unroll
    for (int mt = 0; mt < 2; mt++) {
        const int o_lo = m0 + wm * 32 + mt * 16 + (lane >> 2);
        const int o_hi = o_lo + 8;
        const float bi_lo = bf[o_lo], bi_hi = bf[o_hi];
#pragma unroll
        for (int j = 0; j < 8; j++) {
            const int p = n0 + wn * 64 + j * 8 + 2 * (lane & 3);
            const float2 Sv = *(const float2*)&Sb[p];
            const size_t off0 = ((size_t)(b * Cc + o_lo)) * HW + p;
            const size_t off1 = ((size_t)(b * Cc + o_hi)) * HW + p;
            const float2 f0 = *(const float2*)&front_x[off0];
            const float2 f1 = *(const float2*)&front_x[off1];
            float2 r0, r1;
            r0.x = f0.x + (acc[mt][j][0] + bi_lo) * Sv.x;
            r0.y = f0.y + (acc[mt][j][1] + bi_lo) * Sv.y;
            r1.x = f1.x + (acc[mt][j][2] + bi_hi) * Sv.x;
            r1.y = f1.y + (acc[mt][j][3] + bi_hi) * Sv.y;
            *(float2*)&out[off0] = r0;
            *(float2*)&out[off1] = r1;
        }
    }
}

// ===================== launch ==============================================
extern "C" void kernel_launch(void* const* d_in, const int* in_sizes, int n_in,
                              void* d_out, int out_size) {
    const float* front_x     = (const float*)d_in[0];
    const float* cross_x     = (const float*)d_in[1];
    const float* front_x_hat = (const float*)d_in[2];
    const float* Wq = (const float*)d_in[3];
    const float* bq = (const float*)d_in[4];
    const float* Wk = (const float*)d_in[5];
    const float* bk = (const float*)d_in[6];
    const float* Wv = (const float*)d_in[7];
    const float* bv = (const float*)d_in[8];
    const float* Wf = (const float*)d_in[9];
    const float* bf = (const float*)d_in[10];
    float* out = (float*)d_out;

    cudaFuncSetAttribute(conv_mma, cudaFuncAttributeMaxDynamicSharedMemorySize, 4 * STAGE);
    cudaFuncSetAttribute(v_mma, cudaFuncAttributeMaxDynamicSharedMemorySize, 128 * 132 * 4);

    float* vt;
    cudaGetSymbolAddress((void**)&vt, g_vt);

    prep_w<<<512, 256>>>(Wf);
    prep_wv<<<256, 256>>>(Wv);

    gemm_qk<<<dim3(32, 2, 4), 256>>>(cross_x, front_x, Wq, bq, Wk, bk);
    v_mma<<<dim3(32, 2, 4), 256, 128 * 132 * 4>>>(front_x_hat, bv, vt);

    energy_argmax<<<dim3(32, 4, 4), 128>>>();
    reduce_argmax<<<64, 256>>>();

    fill_xt<<<dim3(16, 64, 4), 256>>>(front_x);

    conv_mma<<<dim3(32, 2, 4), 256, 4 * STAGE>>>(front_x, bf, out);
}